// round 1
// baseline (speedup 1.0000x reference)
#include <cuda_runtime.h>

#define T_ 65536
#define D_ 256
#define CHUNK 128
#define NCH (T_/CHUNK)   // 512

// -------- scratch (device globals; no allocations allowed) --------
__device__ float g_af[T_*D_];   // forward dir: a = 1-z
__device__ float g_bf[T_*D_];   // forward dir: b = z*htilde
__device__ float g_ab2[T_*D_];  // backward dir a
__device__ float g_bb2[T_*D_];  // backward dir b
__device__ float g_hf[T_*D_];   // forward scan states
__device__ float g_hb[T_*D_];   // backward (reverse) scan states
__device__ float g_cA[2*NCH*D_];
__device__ float g_cB[2*NCH*D_];
__device__ float g_pref[2*NCH*D_];

__device__ __forceinline__ float sigf(float v)   { return 1.0f/(1.0f+__expf(-v)); }
__device__ __forceinline__ float tanhf_(float v) { return 1.0f - 2.0f/(__expf(2.0f*v)+1.0f); }

// ---------------- fused GEMM: z preact + htilde preact -> a,b ----------------
// Computes, per row t and output channel d (for one direction):
//   z  = sigmoid( (x_t * q_t) @ Wz[:,d] + bz[d] )
//   ht = tanh( [x_t, q_t] @ Wh[:,d] + bh[d] )
//   a = 1-z ; b = z*ht
// q_t = question (broadcast, qmode=0)  or  g_hf[t]+g_hb[t] (qmode=1).
constexpr int BM = 128, BN = 64, KC = 16;

__global__ __launch_bounds__(256, 2) void gemm_ab(
    const float* __restrict__ x,
    const float* __restrict__ qvec, int qmode,
    const float* __restrict__ Wz, const float* __restrict__ bz,
    const float* __restrict__ Wh, const float* __restrict__ bh,
    int dir)
{
    __shared__ float As[KC][BM];
    __shared__ float Bs[KC][BN];
    const int tid = threadIdx.x;
    const int tx = tid & 15;        // 16 col groups of 4
    const int ty = tid >> 4;        // 16 row groups of 8
    const int row0 = blockIdx.y * BM;
    const int col0 = blockIdx.x * BN;

    float acc[8][4];
    #pragma unroll
    for (int i = 0; i < 8; i++)
        #pragma unroll
        for (int j = 0; j < 4; j++) acc[i][j] = 0.f;

    // ---------------- phase 1: u = x*q, acc = u @ Wz ----------------
    for (int kt = 0; kt < D_; kt += KC) {
        #pragma unroll
        for (int r = 0; r < 2; r++) {
            int v = tid + r*256;
            int m = v >> 2, kq = v & 3;
            int row = row0 + m, kk = kt + kq*4;
            float4 xv = *(const float4*)(x + (size_t)row*D_ + kk);
            float4 qv;
            if (qmode == 0) {
                qv = *(const float4*)(qvec + kk);
            } else {
                float4 h1 = *(const float4*)(g_hf + (size_t)row*D_ + kk);
                float4 h2 = *(const float4*)(g_hb + (size_t)row*D_ + kk);
                qv.x = h1.x+h2.x; qv.y = h1.y+h2.y; qv.z = h1.z+h2.z; qv.w = h1.w+h2.w;
            }
            As[kq*4+0][m] = xv.x*qv.x;
            As[kq*4+1][m] = xv.y*qv.y;
            As[kq*4+2][m] = xv.z*qv.z;
            As[kq*4+3][m] = xv.w*qv.w;
        }
        {
            int k = tid >> 4, nq = tid & 15;
            *(float4*)&Bs[k][nq*4] =
                *(const float4*)(Wz + (size_t)(kt+k)*D_ + col0 + nq*4);
        }
        __syncthreads();
        #pragma unroll
        for (int k = 0; k < KC; k++) {
            float4 a0 = *(float4*)&As[k][ty*8];
            float4 a1 = *(float4*)&As[k][ty*8+4];
            float4 bv = *(float4*)&Bs[k][tx*4];
            float am[8] = {a0.x,a0.y,a0.z,a0.w,a1.x,a1.y,a1.z,a1.w};
            float bm[4] = {bv.x,bv.y,bv.z,bv.w};
            #pragma unroll
            for (int i = 0; i < 8; i++)
                #pragma unroll
                for (int j = 0; j < 4; j++)
                    acc[i][j] = fmaf(am[i], bm[j], acc[i][j]);
        }
        __syncthreads();
    }

    float zreg[8][4];
    #pragma unroll
    for (int i = 0; i < 8; i++)
        #pragma unroll
        for (int j = 0; j < 4; j++) {
            zreg[i][j] = sigf(acc[i][j] + bz[col0 + tx*4 + j]);
            acc[i][j] = 0.f;
        }

    // ---------------- phase 2: acc = [x,q] @ Wh ----------------
    for (int kt = 0; kt < 2*D_; kt += KC) {
        #pragma unroll
        for (int r = 0; r < 2; r++) {
            int v = tid + r*256;
            int m = v >> 2, kq = v & 3;
            int row = row0 + m, kk = kt + kq*4;
            float4 av;
            if (kk < D_) {
                av = *(const float4*)(x + (size_t)row*D_ + kk);
            } else {
                int k2 = kk - D_;
                if (qmode == 0) {
                    av = *(const float4*)(qvec + k2);
                } else {
                    float4 h1 = *(const float4*)(g_hf + (size_t)row*D_ + k2);
                    float4 h2 = *(const float4*)(g_hb + (size_t)row*D_ + k2);
                    av.x = h1.x+h2.x; av.y = h1.y+h2.y; av.z = h1.z+h2.z; av.w = h1.w+h2.w;
                }
            }
            As[kq*4+0][m] = av.x;
            As[kq*4+1][m] = av.y;
            As[kq*4+2][m] = av.z;
            As[kq*4+3][m] = av.w;
        }
        {
            int k = tid >> 4, nq = tid & 15;
            *(float4*)&Bs[k][nq*4] =
                *(const float4*)(Wh + (size_t)(kt+k)*D_ + col0 + nq*4);
        }
        __syncthreads();
        #pragma unroll
        for (int k = 0; k < KC; k++) {
            float4 a0 = *(float4*)&As[k][ty*8];
            float4 a1 = *(float4*)&As[k][ty*8+4];
            float4 bv = *(float4*)&Bs[k][tx*4];
            float am[8] = {a0.x,a0.y,a0.z,a0.w,a1.x,a1.y,a1.z,a1.w};
            float bm[4] = {bv.x,bv.y,bv.z,bv.w};
            #pragma unroll
            for (int i = 0; i < 8; i++)
                #pragma unroll
                for (int j = 0; j < 4; j++)
                    acc[i][j] = fmaf(am[i], bm[j], acc[i][j]);
        }
        __syncthreads();
    }

    // ---------------- epilogue: a = 1-z, b = z*tanh(.) ----------------
    float* Aout = dir ? g_ab2 : g_af;
    float* Bout = dir ? g_bb2 : g_bf;
    #pragma unroll
    for (int i = 0; i < 8; i++) {
        int row = row0 + ty*8 + i;
        float ta[4], tb[4];
        #pragma unroll
        for (int j = 0; j < 4; j++) {
            float ht = tanhf_(acc[i][j] + bh[col0 + tx*4 + j]);
            float z = zreg[i][j];
            ta[j] = 1.0f - z;
            tb[j] = z * ht;
        }
        *(float4*)(Aout + (size_t)row*D_ + col0 + tx*4) = make_float4(ta[0],ta[1],ta[2],ta[3]);
        *(float4*)(Bout + (size_t)row*D_ + col0 + tx*4) = make_float4(tb[0],tb[1],tb[2],tb[3]);
    }
}

// ---------------- chunked linear-recurrence scan ----------------
// dir=0: forward scan over t; dir=1: reverse scan (produces h_bwd_rev[::-1] directly).

__global__ __launch_bounds__(256) void scan_chunks(int dir)
{
    int d = threadIdx.x, ch = blockIdx.x;
    const float* A = dir ? g_ab2 : g_af;
    const float* B = dir ? g_bb2 : g_bf;
    float cA = 1.f, cB = 0.f;
    if (dir == 0) {
        size_t base = (size_t)ch*CHUNK*D_ + d;
        #pragma unroll 4
        for (int j = 0; j < CHUNK; j++) {
            float a = A[base + (size_t)j*D_], b = B[base + (size_t)j*D_];
            cB = fmaf(a, cB, b); cA *= a;
        }
    } else {
        size_t base = ((size_t)ch*CHUNK + CHUNK-1)*D_ + d;
        #pragma unroll 4
        for (int j = 0; j < CHUNK; j++) {
            float a = A[base - (size_t)j*D_], b = B[base - (size_t)j*D_];
            cB = fmaf(a, cB, b); cA *= a;
        }
    }
    g_cA[(dir*NCH + ch)*D_ + d] = cA;
    g_cB[(dir*NCH + ch)*D_ + d] = cB;
}

__global__ __launch_bounds__(256) void scan_prefix(int dir)
{
    int d = threadIdx.x;
    float cB = 0.f;
    if (dir == 0) {
        for (int ch = 0; ch < NCH; ch++) {
            g_pref[ch*D_ + d] = cB;
            cB = fmaf(g_cA[ch*D_ + d], cB, g_cB[ch*D_ + d]);
        }
    } else {
        for (int ch = NCH-1; ch >= 0; ch--) {
            g_pref[(NCH + ch)*D_ + d] = cB;
            cB = fmaf(g_cA[(NCH + ch)*D_ + d], cB, g_cB[(NCH + ch)*D_ + d]);
        }
    }
}

__global__ __launch_bounds__(256) void scan_apply(int dir)
{
    int d = threadIdx.x, ch = blockIdx.x;
    const float* A = dir ? g_ab2 : g_af;
    const float* B = dir ? g_bb2 : g_bf;
    float* H = dir ? g_hb : g_hf;
    float h = g_pref[(dir*NCH + ch)*D_ + d];
    if (dir == 0) {
        size_t base = (size_t)ch*CHUNK*D_ + d;
        #pragma unroll 4
        for (int j = 0; j < CHUNK; j++) {
            size_t o = base + (size_t)j*D_;
            h = fmaf(A[o], h, B[o]);
            H[o] = h;
        }
    } else {
        size_t base = ((size_t)ch*CHUNK + CHUNK-1)*D_ + d;
        #pragma unroll 4
        for (int j = 0; j < CHUNK; j++) {
            size_t o = base - (size_t)j*D_;
            h = fmaf(A[o], h, B[o]);
            H[o] = h;
        }
    }
}

// Last layer: only h_fwd[T-1] is needed == full-sequence composite applied to 0.
__global__ __launch_bounds__(256) void scan_final(float* __restrict__ out)
{
    int d = threadIdx.x;
    float cB = 0.f;
    for (int ch = 0; ch < NCH; ch++)
        cB = fmaf(g_cA[ch*D_ + d], cB, g_cB[ch*D_ + d]);
    out[d] = cB;
}

// ---------------- host launcher ----------------
extern "C" void kernel_launch(void* const* d_in, const int* in_sizes, int n_in,
                              void* d_out, int out_size)
{
    const float* story    = (const float*)d_in[0];
    const float* question = (const float*)d_in[1];
    const float* Wz_f     = (const float*)d_in[2];
    const float* bz_f     = (const float*)d_in[3];
    const float* Wh_f     = (const float*)d_in[4];
    const float* bh_f     = (const float*)d_in[5];
    const float* Wz_b     = (const float*)d_in[6];
    const float* bz_b     = (const float*)d_in[7];
    const float* Wh_b     = (const float*)d_in[8];
    const float* bh_b     = (const float*)d_in[9];
    float* out = (float*)d_out;

    dim3 gg(D_/BN, T_/BM);  // (4, 512): col tile fastest -> row-tile reuse in L2
    for (int l = 0; l < 3; l++) {
        int qmode = (l == 0) ? 0 : 1;
        const float* qv = (l == 0) ? question : (const float*)nullptr;

        gemm_ab<<<gg, 256>>>(story, qv, qmode,
                             Wz_f + (size_t)l*D_*D_,  bz_f + l*D_,
                             Wh_f + (size_t)l*2*D_*D_, bh_f + l*D_, 0);
        if (l < 2)
            gemm_ab<<<gg, 256>>>(story, qv, qmode,
                                 Wz_b + (size_t)l*D_*D_,  bz_b + l*D_,
                                 Wh_b + (size_t)l*2*D_*D_, bh_b + l*D_, 1);

        scan_chunks<<<NCH, 256>>>(0);
        if (l < 2) {
            scan_chunks<<<NCH, 256>>>(1);
            scan_prefix<<<1, 256>>>(0);
            scan_prefix<<<1, 256>>>(1);
            scan_apply<<<NCH, 256>>>(0);
            scan_apply<<<NCH, 256>>>(1);
        } else {
            scan_final<<<1, 256>>>(out);
        }
    }
}

// round 4
// speedup vs baseline: 1.9201x; 1.9201x over previous
#include <cuda_runtime.h>
#include <cuda_bf16.h>
#include <cstdint>

#define T_ 65536
#define D_ 256
#define CHUNK 128
#define NCH (T_/CHUNK)   // 512

// ================= device scratch (no allocations allowed) =================
__device__ float g_af [T_*D_];
__device__ float g_bf [T_*D_];
__device__ float g_ab2[T_*D_];
__device__ float g_bb2[T_*D_];
__device__ float g_q  [T_*D_];          // h_fwd, then q = h_fwd + h_bwd
__device__ float g_cA [2*NCH*D_];
__device__ float g_cB [2*NCH*D_];
__device__ float g_pref[2*NCH*D_];
__device__ float g_hbias[2][D_];        // layer0: bh + q0 @ Wh_bottom

__device__ __nv_bfloat16 g_xhi[T_*D_], g_xlo[T_*D_];
__device__ __nv_bfloat16 g_uhi[T_*D_], g_ulo[T_*D_];
__device__ __nv_bfloat16 g_qhi[T_*D_], g_qlo[T_*D_];
__device__ __nv_bfloat16 g_wzT[5][2][D_*D_];     // [layerdir][hi/lo][n*256+k]
__device__ __nv_bfloat16 g_whT[5][2][D_*2*D_];   // [layerdir][hi/lo][n*512+k]

// ================= helpers =================
__device__ __forceinline__ uint32_t smem_u32(const void* p) {
    uint32_t a;
    asm("{ .reg .u64 t; cvta.to.shared.u64 t, %1; cvt.u32.u64 %0, t; }" : "=r"(a) : "l"(p));
    return a;
}
__device__ __forceinline__ void ldsm_x4(uint32_t (&r)[4], uint32_t addr) {
    asm volatile("ldmatrix.sync.aligned.m8n8.x4.shared.b16 {%0,%1,%2,%3}, [%4];"
                 : "=r"(r[0]), "=r"(r[1]), "=r"(r[2]), "=r"(r[3]) : "r"(addr));
}
__device__ __forceinline__ void mma16816(float (&d)[4], const uint32_t (&a)[4], const uint32_t* b) {
    asm volatile("mma.sync.aligned.m16n8k16.row.col.f32.bf16.bf16.f32 "
                 "{%0,%1,%2,%3}, {%4,%5,%6,%7}, {%8,%9}, {%0,%1,%2,%3};"
                 : "+f"(d[0]), "+f"(d[1]), "+f"(d[2]), "+f"(d[3])
                 : "r"(a[0]), "r"(a[1]), "r"(a[2]), "r"(a[3]), "r"(b[0]), "r"(b[1]));
}
__device__ __forceinline__ float sigf(float v)   { return 1.0f/(1.0f+__expf(-v)); }
__device__ __forceinline__ float tanhf_(float v) { return 1.0f - 2.0f/(__expf(2.0f*v)+1.0f); }
__device__ __forceinline__ void split2(float v, __nv_bfloat16& h, __nv_bfloat16& l) {
    h = __float2bfloat16(v);
    l = __float2bfloat16(v - __bfloat162float(h));
}

// ================= prep kernels =================
__global__ void prep_w(const float* __restrict__ Wz, const float* __restrict__ Wh, int ld)
{
    int mz = blockIdx.z;                  // 0: Wz (K=256), 1: Wh (K=512)
    if (mz == 0 && blockIdx.y >= 8) return;
    const float* src = mz ? Wh : Wz;
    int Krows = mz ? 512 : 256;
    __nv_bfloat16* dh = mz ? &g_whT[ld][0][0] : &g_wzT[ld][0][0];
    __nv_bfloat16* dl = mz ? &g_whT[ld][1][0] : &g_wzT[ld][1][0];
    int k0 = blockIdx.y*32, n0 = blockIdx.x*32;
    int tx = threadIdx.x, ty = threadIdx.y;
    __shared__ float t[32][33];
    #pragma unroll
    for (int i = 0; i < 4; i++)
        t[ty + i*8][tx] = src[(size_t)(k0 + ty + i*8)*256 + n0 + tx];
    __syncthreads();
    #pragma unroll
    for (int i = 0; i < 4; i++) {
        float v = t[tx][ty + i*8];
        __nv_bfloat16 h, l; split2(v, h, l);
        size_t o = (size_t)(n0 + ty + i*8)*Krows + k0 + tx;
        dh[o] = h; dl[o] = l;
    }
}

__global__ void prep_x(const float* __restrict__ story)
{
    size_t i = ((size_t)blockIdx.x*256 + threadIdx.x)*2;
    float2 v = *(const float2*)(story + i);
    __nv_bfloat16 h0,l0,h1,l1; split2(v.x,h0,l0); split2(v.y,h1,l1);
    __nv_bfloat162 ph, pl; ph.x=h0; ph.y=h1; pl.x=l0; pl.y=l1;
    *(__nv_bfloat162*)(g_xhi+i) = ph; *(__nv_bfloat162*)(g_xlo+i) = pl;
}

__global__ void prep_u0(const float* __restrict__ story, const float* __restrict__ q)
{
    size_t i = ((size_t)blockIdx.x*256 + threadIdx.x)*2;
    int d = (int)(i & (D_-1));
    float2 v = *(const float2*)(story + i);
    float u0 = v.x * q[d], u1 = v.y * q[d+1];
    __nv_bfloat16 h0,l0,h1,l1; split2(u0,h0,l0); split2(u1,h1,l1);
    __nv_bfloat162 ph, pl; ph.x=h0; ph.y=h1; pl.x=l0; pl.y=l1;
    *(__nv_bfloat162*)(g_uhi+i) = ph; *(__nv_bfloat162*)(g_ulo+i) = pl;
}

__global__ void qwh0(const float* __restrict__ Whf, const float* __restrict__ bhf,
                     const float* __restrict__ Whb, const float* __restrict__ bhb,
                     const float* __restrict__ q)
{
    int dir = blockIdx.x, n = threadIdx.x;
    const float* Wh = dir ? Whb : Whf;
    const float* bh = dir ? bhb : bhf;
    float acc = bh[n];
    #pragma unroll 8
    for (int k = 0; k < 256; k++)
        acc = fmaf(q[k], Wh[(size_t)(256 + k)*256 + n], acc);
    g_hbias[dir][n] = acc;
}

// ================= fused GEMM (mma.sync bf16 split) =================
// CTA: M=128 rows (one scan chunk) x N=128 channels (half). 8 warps = 4M x 2N.
// Dynamic SMEM map:
//   [0, 40960)      : operand tiles Ahi/Alo/Bhi/Blo, each 128x(32+8pad) bf16 = 10240B
//   [0, 67584)      : (aliased after MMA) bbuf 128x132 fp32
//   [67584, 135168) : zbuf/abuf 128x132 fp32
#define SM_TOTAL 135168
#define TSTR 40     // smem tile row stride in bf16 elems (80 bytes)

struct Pref { float4 ah[2], al[2], bh[2], bl[2]; };

__device__ __forceinline__ void g_load(Pref& P,
    const __nv_bfloat16* Ah, const __nv_bfloat16* Al, int row0, int ka,
    const __nv_bfloat16* Bh, const __nv_bfloat16* Bl, int n0, int Kdim, int kb, int tid)
{
    #pragma unroll
    for (int i = 0; i < 2; i++) {
        int idx = tid + i*256, r = idx >> 2, q = idx & 3;
        size_t oa = (size_t)(row0 + r)*256 + ka + q*8;
        P.ah[i] = *(const float4*)(Ah + oa);
        P.al[i] = *(const float4*)(Al + oa);
        size_t ob = (size_t)(n0 + r)*Kdim + kb + q*8;
        P.bh[i] = *(const float4*)(Bh + ob);
        P.bl[i] = *(const float4*)(Bl + ob);
    }
}

__device__ __forceinline__ void s_store(const Pref& P, __nv_bfloat16* sb, int tid)
{
    #pragma unroll
    for (int i = 0; i < 2; i++) {
        int idx = tid + i*256, r = idx >> 2, q = idx & 3;
        int off = r*TSTR + q*8;
        *(float4*)(sb + 0*5120 + off) = P.ah[i];
        *(float4*)(sb + 1*5120 + off) = P.al[i];
        *(float4*)(sb + 2*5120 + off) = P.bh[i];
        *(float4*)(sb + 3*5120 + off) = P.bl[i];
    }
}

__device__ __forceinline__ void mma_step(float (&acc)[2][8][4],
    uint32_t uA, uint32_t uB, int wm, int wn, int lane)
{
    #pragma unroll
    for (int kk = 0; kk < 32; kk += 16) {
        uint32_t aH[2][4], aL[2][4], bH[8][2], bL[8][2];
        #pragma unroll
        for (int mi = 0; mi < 2; mi++) {
            uint32_t roff = (uint32_t)(wm*32 + mi*16 + (lane & 15))*(TSTR*2)
                          + (uint32_t)(kk + ((lane >> 4) << 3))*2;
            ldsm_x4(aH[mi], uA + roff);
            ldsm_x4(aL[mi], uA + 10240 + roff);
        }
        #pragma unroll
        for (int pi = 0; pi < 4; pi++) {
            uint32_t nrow = (uint32_t)(wn*64 + pi*16 + ((lane >> 4) << 3) + (lane & 7));
            uint32_t off = nrow*(TSTR*2) + (uint32_t)(kk + (((lane >> 3) & 1) << 3))*2;
            uint32_t t[4];
            ldsm_x4(t, uB + off);
            bH[pi*2][0]=t[0]; bH[pi*2][1]=t[1]; bH[pi*2+1][0]=t[2]; bH[pi*2+1][1]=t[3];
            ldsm_x4(t, uB + 10240 + off);
            bL[pi*2][0]=t[0]; bL[pi*2][1]=t[1]; bL[pi*2+1][0]=t[2]; bL[pi*2+1][1]=t[3];
        }
        #pragma unroll
        for (int mi = 0; mi < 2; mi++)
            #pragma unroll
            for (int ni = 0; ni < 8; ni++) {
                mma16816(acc[mi][ni], aH[mi], bH[ni]);
                mma16816(acc[mi][ni], aH[mi], bL[ni]);
                mma16816(acc[mi][ni], aL[mi], bH[ni]);
            }
    }
}

__global__ __launch_bounds__(256, 1)
void qrn_gemm(int ld, int layer0, int dir, int store_ab,
              const float* __restrict__ bz, const float* __restrict__ bhp)
{
    extern __shared__ __align__(16) char smem[];
    __nv_bfloat16* sOp = (__nv_bfloat16*)smem;       // 4 tiles x 5120 bf16
    float* bbuf = (float*)smem;                      // aliases operands (post-MMA)
    float* zbuf = (float*)(smem + 67584);            // z then a
    __shared__ float s_bz[128], s_bh[128];
    __shared__ float s_pA[2][128], s_pB[2][128];

    const int tid = threadIdx.x, lane = tid & 31, warp = tid >> 5;
    const int wm = warp & 3, wn = warp >> 2;
    const int nh = blockIdx.x, ch = blockIdx.y;
    const int row0 = ch*CHUNK, n0g = nh*128;
    const uint32_t uA = smem_u32(sOp);
    const uint32_t uB = uA + 20480;

    if (tid < 128) {
        s_bz[tid] = bz[n0g + tid];
        s_bh[tid] = layer0 ? g_hbias[dir][n0g + tid] : bhp[n0g + tid];
    }

    float acc[2][8][4];
    Pref P;

    // =============== phase Z: u @ Wz (K=256) ===============
    #pragma unroll
    for (int mi = 0; mi < 2; mi++)
        #pragma unroll
        for (int ni = 0; ni < 8; ni++)
            #pragma unroll
            for (int j = 0; j < 4; j++) acc[mi][ni][j] = 0.f;

    const __nv_bfloat16* wzh = &g_wzT[ld][0][0];
    const __nv_bfloat16* wzl = &g_wzT[ld][1][0];
    g_load(P, g_uhi, g_ulo, row0, 0, wzh, wzl, n0g, 256, 0, tid);
    for (int s = 0; s < 8; s++) {
        __syncthreads();
        s_store(P, sOp, tid);
        __syncthreads();
        if (s + 1 < 8)
            g_load(P, g_uhi, g_ulo, row0, (s+1)*32, wzh, wzl, n0g, 256, (s+1)*32, tid);
        mma_step(acc, uA, uB, wm, wn, lane);
    }

    // z epilogue -> zbuf (separate smem region; no sync needed vs operands)
    #pragma unroll
    for (int mi = 0; mi < 2; mi++) {
        int r0 = wm*32 + mi*16 + (lane >> 2);
        #pragma unroll
        for (int ni = 0; ni < 8; ni++) {
            int cl = wn*64 + ni*8 + (lane & 3)*2;
            zbuf[r0*132 + cl]     = sigf(acc[mi][ni][0] + s_bz[cl]);
            zbuf[r0*132 + cl + 1] = sigf(acc[mi][ni][1] + s_bz[cl+1]);
            zbuf[(r0+8)*132 + cl]     = sigf(acc[mi][ni][2] + s_bz[cl]);
            zbuf[(r0+8)*132 + cl + 1] = sigf(acc[mi][ni][3] + s_bz[cl+1]);
        }
    }

    // =============== phase H: [x,q] @ Wh (K=512; layer0: x only, q folded into bias) ===============
    #pragma unroll
    for (int mi = 0; mi < 2; mi++)
        #pragma unroll
        for (int ni = 0; ni < 8; ni++)
            #pragma unroll
            for (int j = 0; j < 4; j++) acc[mi][ni][j] = 0.f;

    const __nv_bfloat16* whh = &g_whT[ld][0][0];
    const __nv_bfloat16* whl = &g_whT[ld][1][0];
    const int nH = layer0 ? 8 : 16;
    g_load(P, g_xhi, g_xlo, row0, 0, whh, whl, n0g, 512, 0, tid);
    for (int s = 0; s < nH; s++) {
        __syncthreads();
        s_store(P, sOp, tid);
        __syncthreads();
        if (s + 1 < nH) {
            int s2 = s + 1;
            const __nv_bfloat16* Ah = (s2 < 8) ? g_xhi : g_qhi;
            const __nv_bfloat16* Al = (s2 < 8) ? g_xlo : g_qlo;
            int ka = ((s2 < 8) ? s2 : s2 - 8)*32;
            g_load(P, Ah, Al, row0, ka, whh, whl, n0g, 512, s2*32, tid);
        }
        mma_step(acc, uA, uB, wm, wn, lane);
    }
    __syncthreads();   // all MMA done; operand smem reusable as bbuf

    // ---- final epilogue: a = 1-z (in place), b = z*tanh(h+bh) -> bbuf ----
    #pragma unroll
    for (int mi = 0; mi < 2; mi++) {
        int r0 = wm*32 + mi*16 + (lane >> 2);
        #pragma unroll
        for (int ni = 0; ni < 8; ni++) {
            int cl = wn*64 + ni*8 + (lane & 3)*2;
            #pragma unroll
            for (int hrow = 0; hrow < 2; hrow++) {
                int r = r0 + hrow*8;
                float z0 = zbuf[r*132 + cl], z1 = zbuf[r*132 + cl + 1];
                float h0 = tanhf_(acc[mi][ni][hrow*2+0] + s_bh[cl]);
                float h1 = tanhf_(acc[mi][ni][hrow*2+1] + s_bh[cl+1]);
                bbuf[r*132 + cl]     = z0*h0;
                bbuf[r*132 + cl + 1] = z1*h1;
                zbuf[r*132 + cl]     = 1.0f - z0;
                zbuf[r*132 + cl + 1] = 1.0f - z1;
            }
        }
    }
    __syncthreads();

    // ---- global a,b stores ----
    if (store_ab) {
        float* outA = dir ? g_ab2 : g_af;
        float* outB = dir ? g_bb2 : g_bf;
        #pragma unroll
        for (int i = 0; i < 16; i++) {
            int r = (tid >> 5) + i*8;
            int c4 = (tid & 31)*4;
            float4 va = *(float4*)(zbuf + r*132 + c4);
            float4 vb = *(float4*)(bbuf + r*132 + c4);
            size_t o = (size_t)(row0 + r)*256 + n0g + c4;
            *(float4*)(outA + o) = va;
            *(float4*)(outB + o) = vb;
        }
    }

    // ---- per-chunk scan composites ----
    {
        int cc = tid & 127, seg = tid >> 7;
        float pa = 1.0f, pb = 0.0f;
        if (dir == 0) {
            for (int r = seg*64; r < seg*64 + 64; r++) {
                float a = zbuf[r*132 + cc], b = bbuf[r*132 + cc];
                pb = fmaf(a, pb, b); pa *= a;
            }
        } else {
            for (int r = seg*64 + 63; r >= seg*64; r--) {
                float a = zbuf[r*132 + cc], b = bbuf[r*132 + cc];
                pb = fmaf(a, pb, b); pa *= a;
            }
        }
        s_pA[seg][cc] = pa; s_pB[seg][cc] = pb;
    }
    __syncthreads();
    if (tid < 128) {
        float A, B;
        if (dir == 0) { A = s_pA[1][tid]*s_pA[0][tid]; B = fmaf(s_pA[1][tid], s_pB[0][tid], s_pB[1][tid]); }
        else          { A = s_pA[0][tid]*s_pA[1][tid]; B = fmaf(s_pA[0][tid], s_pB[1][tid], s_pB[0][tid]); }
        size_t o = ((size_t)dir*NCH + ch)*256 + n0g + tid;
        g_cA[o] = A; g_cB[o] = B;
    }
}

// ================= scan kernels =================
__global__ __launch_bounds__(256) void scan_prefix()
{
    int dir = blockIdx.x, d = threadIdx.x;
    float cB = 0.f;
    if (dir == 0) {
        for (int ch = 0; ch < NCH; ch++) {
            g_pref[ch*D_ + d] = cB;
            cB = fmaf(g_cA[ch*D_ + d], cB, g_cB[ch*D_ + d]);
        }
    } else {
        for (int ch = NCH-1; ch >= 0; ch--) {
            g_pref[(NCH + ch)*D_ + d] = cB;
            cB = fmaf(g_cA[(NCH + ch)*D_ + d], cB, g_cB[(NCH + ch)*D_ + d]);
        }
    }
}

__global__ __launch_bounds__(256) void scan_apply0()
{
    int d = threadIdx.x, ch = blockIdx.x;
    float h = g_pref[ch*D_ + d];
    size_t base = (size_t)ch*CHUNK*D_ + d;
    #pragma unroll 4
    for (int j = 0; j < CHUNK; j++) {
        size_t o = base + (size_t)j*D_;
        h = fmaf(g_af[o], h, g_bf[o]);
        g_q[o] = h;
    }
}

__global__ __launch_bounds__(256) void scan_apply1(const float* __restrict__ story)
{
    int d = threadIdx.x, ch = blockIdx.x;
    float h = g_pref[(NCH + ch)*D_ + d];
    size_t base = ((size_t)ch*CHUNK + CHUNK-1)*D_ + d;
    #pragma unroll 4
    for (int j = 0; j < CHUNK; j++) {
        size_t o = base - (size_t)j*D_;
        h = fmaf(g_ab2[o], h, g_bb2[o]);
        float q = g_q[o] + h;
        float u = story[o] * q;
        __nv_bfloat16 qh, ql, uh, ul;
        split2(q, qh, ql); split2(u, uh, ul);
        g_qhi[o] = qh; g_qlo[o] = ql; g_uhi[o] = uh; g_ulo[o] = ul;
    }
}

__global__ __launch_bounds__(256) void scan_final(float* __restrict__ out)
{
    int d = threadIdx.x;
    float cB = 0.f;
    for (int ch = 0; ch < NCH; ch++)
        cB = fmaf(g_cA[ch*D_ + d], cB, g_cB[ch*D_ + d]);
    out[d] = cB;
}

// ================= host launcher =================
extern "C" void kernel_launch(void* const* d_in, const int* in_sizes, int n_in,
                              void* d_out, int out_size)
{
    const float* story    = (const float*)d_in[0];
    const float* question = (const float*)d_in[1];
    const float* Wz_f     = (const float*)d_in[2];
    const float* bz_f     = (const float*)d_in[3];
    const float* Wh_f     = (const float*)d_in[4];
    const float* bh_f     = (const float*)d_in[5];
    const float* Wz_b     = (const float*)d_in[6];
    const float* bz_b     = (const float*)d_in[7];
    const float* Wh_b     = (const float*)d_in[8];
    const float* bh_b     = (const float*)d_in[9];
    float* out = (float*)d_out;

    cudaFuncSetAttribute(qrn_gemm, cudaFuncAttributeMaxDynamicSharedMemorySize, SM_TOTAL);

    // weight prep: layerdir 0..4 = (f0, b0, f1, b1, f2)
    dim3 wb(32, 8), wg(8, 16, 2);
    prep_w<<<wg, wb>>>(Wz_f,            Wh_f,             0);
    prep_w<<<wg, wb>>>(Wz_b,            Wh_b,             1);
    prep_w<<<wg, wb>>>(Wz_f + 65536,    Wh_f + 131072,    2);
    prep_w<<<wg, wb>>>(Wz_b + 65536,    Wh_b + 131072,    3);
    prep_w<<<wg, wb>>>(Wz_f + 2*65536,  Wh_f + 2*131072,  4);

    prep_x<<<T_*D_/512, 256>>>(story);
    qwh0<<<2, 256>>>(Wh_f, bh_f, Wh_b, bh_b, question);
    prep_u0<<<T_*D_/512, 256>>>(story, question);

    dim3 gg(2, NCH);   // (N-half, chunk)

    // ---- layer 0 ----
    qrn_gemm<<<gg, 256, SM_TOTAL>>>(0, 1, 0, 1, bz_f,        nullptr);
    qrn_gemm<<<gg, 256, SM_TOTAL>>>(1, 1, 1, 1, bz_b,        nullptr);
    scan_prefix<<<2, 256>>>();
    scan_apply0<<<NCH, 256>>>();
    scan_apply1<<<NCH, 256>>>(story);

    // ---- layer 1 ----
    qrn_gemm<<<gg, 256, SM_TOTAL>>>(2, 0, 0, 1, bz_f + 256,  bh_f + 256);
    qrn_gemm<<<gg, 256, SM_TOTAL>>>(3, 0, 1, 1, bz_b + 256,  bh_b + 256);
    scan_prefix<<<2, 256>>>();
    scan_apply0<<<NCH, 256>>>();
    scan_apply1<<<NCH, 256>>>(story);

    // ---- layer 2 (forward only; only final state needed -> composites only) ----
    qrn_gemm<<<gg, 256, SM_TOTAL>>>(4, 0, 0, 0, bz_f + 512,  bh_f + 512);
    scan_final<<<1, 256>>>(out);
}

// round 6
// speedup vs baseline: 2.5212x; 1.3131x over previous
#include <cuda_runtime.h>
#include <cuda_bf16.h>
#include <cstdint>

#define T_ 65536
#define D_ 256
#define CHUNK 128
#define NCH (T_/CHUNK)   // 512

// ================= device scratch (no allocations allowed) =================
__device__ float g_af [T_*D_];
__device__ float g_bf [T_*D_];
__device__ float g_ab2[T_*D_];
__device__ float g_bb2[T_*D_];
__device__ float g_q  [T_*D_];          // h_fwd, then q = h_fwd + h_bwd
__device__ float g_cA [2*NCH*D_];
__device__ float g_cB [2*NCH*D_];
__device__ float g_pref[2*NCH*D_];
__device__ float g_hbias[2][D_];        // layer0: bh + q0 @ Wh_bottom

__device__ __nv_bfloat16 g_xhi[T_*D_], g_xlo[T_*D_];
__device__ __nv_bfloat16 g_uhi[T_*D_], g_ulo[T_*D_];
__device__ __nv_bfloat16 g_qhi[T_*D_], g_qlo[T_*D_];
__device__ __nv_bfloat16 g_wzT[5][2][D_*D_];     // [layerdir][hi/lo][n*256+k]
__device__ __nv_bfloat16 g_whT[5][2][D_*2*D_];   // [layerdir][hi/lo][n*512+k]

// ================= helpers =================
__device__ __forceinline__ uint32_t smem_u32(const void* p) {
    uint32_t a;
    asm("{ .reg .u64 t; cvta.to.shared.u64 t, %1; cvt.u32.u64 %0, t; }" : "=r"(a) : "l"(p));
    return a;
}
__device__ __forceinline__ void ldsm_x4(uint32_t (&r)[4], uint32_t addr) {
    asm volatile("ldmatrix.sync.aligned.m8n8.x4.shared.b16 {%0,%1,%2,%3}, [%4];"
                 : "=r"(r[0]), "=r"(r[1]), "=r"(r[2]), "=r"(r[3]) : "r"(addr));
}
__device__ __forceinline__ void mma16816(float (&d)[4], const uint32_t (&a)[4], const uint32_t* b) {
    asm volatile("mma.sync.aligned.m16n8k16.row.col.f32.bf16.bf16.f32 "
                 "{%0,%1,%2,%3}, {%4,%5,%6,%7}, {%8,%9}, {%0,%1,%2,%3};"
                 : "+f"(d[0]), "+f"(d[1]), "+f"(d[2]), "+f"(d[3])
                 : "r"(a[0]), "r"(a[1]), "r"(a[2]), "r"(a[3]), "r"(b[0]), "r"(b[1]));
}
__device__ __forceinline__ void cpa16(uint32_t dst, const void* src) {
    asm volatile("cp.async.cg.shared.global [%0], [%1], 16;" :: "r"(dst), "l"(src));
}
#define CP_COMMIT() asm volatile("cp.async.commit_group;" ::: "memory")
#define CP_WAIT1()  asm volatile("cp.async.wait_group 1;" ::: "memory")

__device__ __forceinline__ float sigf(float v)   { return 1.0f/(1.0f+__expf(-v)); }
__device__ __forceinline__ float tanhf_(float v) { return 1.0f - 2.0f/(__expf(2.0f*v)+1.0f); }
__device__ __forceinline__ void split2(float v, __nv_bfloat16& h, __nv_bfloat16& l) {
    h = __float2bfloat16(v);
    l = __float2bfloat16(v - __bfloat162float(h));
}

// ================= prep kernels =================
__global__ void prep_w(const float* __restrict__ Wz, const float* __restrict__ Wh, int ld)
{
    int mz = blockIdx.z;                  // 0: Wz (K=256), 1: Wh (K=512)
    if (mz == 0 && blockIdx.y >= 8) return;
    const float* src = mz ? Wh : Wz;
    int Krows = mz ? 512 : 256;
    __nv_bfloat16* dh = mz ? &g_whT[ld][0][0] : &g_wzT[ld][0][0];
    __nv_bfloat16* dl = mz ? &g_whT[ld][1][0] : &g_wzT[ld][1][0];
    int k0 = blockIdx.y*32, n0 = blockIdx.x*32;
    int tx = threadIdx.x, ty = threadIdx.y;
    __shared__ float t[32][33];
    #pragma unroll
    for (int i = 0; i < 4; i++)
        t[ty + i*8][tx] = src[(size_t)(k0 + ty + i*8)*256 + n0 + tx];
    __syncthreads();
    #pragma unroll
    for (int i = 0; i < 4; i++) {
        float v = t[tx][ty + i*8];
        __nv_bfloat16 h, l; split2(v, h, l);
        size_t o = (size_t)(n0 + ty + i*8)*Krows + k0 + tx;
        dh[o] = h; dl[o] = l;
    }
}

// fused: x splits + u0 = x*q splits (single story read)
__global__ void prep_xu(const float* __restrict__ story, const float* __restrict__ q)
{
    size_t i = ((size_t)blockIdx.x*256 + threadIdx.x)*2;
    int d = (int)(i & (D_-1));
    float2 v = *(const float2*)(story + i);
    __nv_bfloat16 h0,l0,h1,l1;
    split2(v.x,h0,l0); split2(v.y,h1,l1);
    __nv_bfloat162 ph, pl; ph.x=h0; ph.y=h1; pl.x=l0; pl.y=l1;
    *(__nv_bfloat162*)(g_xhi+i) = ph; *(__nv_bfloat162*)(g_xlo+i) = pl;
    float u0 = v.x * q[d], u1 = v.y * q[d+1];
    split2(u0,h0,l0); split2(u1,h1,l1);
    ph.x=h0; ph.y=h1; pl.x=l0; pl.y=l1;
    *(__nv_bfloat162*)(g_uhi+i) = ph; *(__nv_bfloat162*)(g_ulo+i) = pl;
}

__global__ void qwh0(const float* __restrict__ Whf, const float* __restrict__ bhf,
                     const float* __restrict__ Whb, const float* __restrict__ bhb,
                     const float* __restrict__ q)
{
    int dir = blockIdx.x, n = threadIdx.x;
    const float* Wh = dir ? Whb : Whf;
    const float* bh = dir ? bhb : bhf;
    float acc = bh[n];
    #pragma unroll 8
    for (int k = 0; k < 256; k++)
        acc = fmaf(q[k], Wh[(size_t)(256 + k)*256 + n], acc);
    g_hbias[dir][n] = acc;
}

// ================= fused GEMM (mma.sync bf16 split, cp.async pipeline) =================
// CTA: M=128 rows (one scan chunk) x N=128 channels (half). 8 warps = 4M x 2N.
// Dynamic SMEM:
//   [0, 122880)        : 3 operand stages x 40960B (Ahi|Alo|Bhi|Blo, each 128x40 bf16)
//   [0, 67584)         : (aliased post-mainloop) bbuf 128x132 fp32
//   [122880, 190464)   : zbuf 128x132 fp32
#define STAGE_B 40960
#define NSTAGE 3
#define ZBUF_OFF (NSTAGE*STAGE_B)
#define SM_TOTAL (ZBUF_OFF + 67584)
#define TSTR 40     // smem tile row stride in bf16 elems (80 bytes)

__device__ __forceinline__ void issue_stage(int s, uint32_t sb,
    int row0, int n0g,
    const __nv_bfloat16* wzh, const __nv_bfloat16* wzl,
    const __nv_bfloat16* whh, const __nv_bfloat16* whl, int tid)
{
    const __nv_bfloat16 *Ah, *Al, *Bh, *Bl; int ka, kb, Kd;
    if (s < 8)       { Ah=g_uhi; Al=g_ulo; Bh=wzh; Bl=wzl; ka=s*32;      kb=s*32;     Kd=256; }
    else if (s < 16) { Ah=g_xhi; Al=g_xlo; Bh=whh; Bl=whl; ka=(s-8)*32;  kb=(s-8)*32; Kd=512; }
    else             { Ah=g_qhi; Al=g_qlo; Bh=whh; Bl=whl; ka=(s-16)*32; kb=(s-8)*32; Kd=512; }
    #pragma unroll
    for (int i = 0; i < 8; i++) {
        int t = i >> 1;                   // tile: 0=Ahi 1=Alo 2=Bhi 3=Blo
        int c = ((i & 1) << 8) + tid;     // 0..511
        int r = c >> 2, q = c & 3;
        const __nv_bfloat16* sp = (t==0) ? Ah : (t==1) ? Al : (t==2) ? Bh : Bl;
        size_t so = (t < 2) ? ((size_t)(row0 + r)*256 + ka + q*8)
                            : ((size_t)(n0g + r)*Kd  + kb + q*8);
        uint32_t d = sb + (uint32_t)(t*10240 + r*80 + q*16);
        cpa16(d, sp + so);
    }
}

__device__ __forceinline__ void mma_step(float (&acc)[2][8][4],
    uint32_t uA, uint32_t uB, int wm, int wn, int lane)
{
    #pragma unroll
    for (int kk = 0; kk < 32; kk += 16) {
        uint32_t aH[2][4], aL[2][4], bH[8][2], bL[8][2];
        #pragma unroll
        for (int mi = 0; mi < 2; mi++) {
            uint32_t roff = (uint32_t)(wm*32 + mi*16 + (lane & 15))*(TSTR*2)
                          + (uint32_t)(kk + ((lane >> 4) << 3))*2;
            ldsm_x4(aH[mi], uA + roff);
            ldsm_x4(aL[mi], uA + 10240 + roff);
        }
        #pragma unroll
        for (int pi = 0; pi < 4; pi++) {
            uint32_t nrow = (uint32_t)(wn*64 + pi*16 + ((lane >> 4) << 3) + (lane & 7));
            uint32_t off = nrow*(TSTR*2) + (uint32_t)(kk + (((lane >> 3) & 1) << 3))*2;
            uint32_t t[4];
            ldsm_x4(t, uB + off);
            bH[pi*2][0]=t[0]; bH[pi*2][1]=t[1]; bH[pi*2+1][0]=t[2]; bH[pi*2+1][1]=t[3];
            ldsm_x4(t, uB + 10240 + off);
            bL[pi*2][0]=t[0]; bL[pi*2][1]=t[1]; bL[pi*2+1][0]=t[2]; bL[pi*2+1][1]=t[3];
        }
        #pragma unroll
        for (int mi = 0; mi < 2; mi++)
            #pragma unroll
            for (int ni = 0; ni < 8; ni++) {
                mma16816(acc[mi][ni], aH[mi], bH[ni]);
                mma16816(acc[mi][ni], aH[mi], bL[ni]);
                mma16816(acc[mi][ni], aL[mi], bH[ni]);
            }
    }
}

__global__ __launch_bounds__(256, 1)
void qrn_gemm(int ld, int layer0, int dir, int store_ab,
              const float* __restrict__ bz, const float* __restrict__ bhp)
{
    extern __shared__ __align__(16) char smem[];
    float* bbuf = (float*)smem;                      // aliases operand stages (post-mainloop)
    float* zbuf = (float*)(smem + ZBUF_OFF);
    __shared__ float s_bz[128], s_bh[128];
    __shared__ float s_pA[2][128], s_pB[2][128];

    const int tid = threadIdx.x, lane = tid & 31, warp = tid >> 5;
    const int wm = warp & 3, wn = warp >> 2;
    const int nh = blockIdx.x, ch = blockIdx.y;
    const int row0 = ch*CHUNK, n0g = nh*128;
    const uint32_t base = smem_u32(smem);

    if (tid < 128) {
        s_bz[tid] = bz[n0g + tid];
        s_bh[tid] = layer0 ? g_hbias[dir][n0g + tid] : bhp[n0g + tid];
    }

    const __nv_bfloat16* wzh = &g_wzT[ld][0][0];
    const __nv_bfloat16* wzl = &g_wzT[ld][1][0];
    const __nv_bfloat16* whh = &g_whT[ld][0][0];
    const __nv_bfloat16* whl = &g_whT[ld][1][0];

    const int S = layer0 ? 16 : 24;     // 8 Z-steps + 8/16 H-steps

    float acc[2][8][4];
    #pragma unroll
    for (int mi = 0; mi < 2; mi++)
        #pragma unroll
        for (int ni = 0; ni < 8; ni++)
            #pragma unroll
            for (int j = 0; j < 4; j++) acc[mi][ni][j] = 0.f;

    // prologue: stages 0,1 in flight
    issue_stage(0, base + 0*STAGE_B, row0, n0g, wzh, wzl, whh, whl, tid);
    CP_COMMIT();
    issue_stage(1, base + 1*STAGE_B, row0, n0g, wzh, wzl, whh, whl, tid);
    CP_COMMIT();

    for (int s = 0; s < S; s++) {
        CP_WAIT1();            // stage s resident
        __syncthreads();
        if (s + 2 < S)
            issue_stage(s+2, base + ((s+2) % NSTAGE)*STAGE_B, row0, n0g, wzh, wzl, whh, whl, tid);
        CP_COMMIT();           // empty group when nothing issued keeps accounting uniform

        uint32_t uA = base + (s % NSTAGE)*STAGE_B;
        mma_step(acc, uA, uA + 20480, wm, wn, lane);

        if (s == 7) {
            // z epilogue -> zbuf, reset acc for H phase
            #pragma unroll
            for (int mi = 0; mi < 2; mi++) {
                int r0 = wm*32 + mi*16 + (lane >> 2);
                #pragma unroll
                for (int ni = 0; ni < 8; ni++) {
                    int cl = wn*64 + ni*8 + (lane & 3)*2;
                    zbuf[r0*132 + cl]     = sigf(acc[mi][ni][0] + s_bz[cl]);
                    zbuf[r0*132 + cl + 1] = sigf(acc[mi][ni][1] + s_bz[cl+1]);
                    zbuf[(r0+8)*132 + cl]     = sigf(acc[mi][ni][2] + s_bz[cl]);
                    zbuf[(r0+8)*132 + cl + 1] = sigf(acc[mi][ni][3] + s_bz[cl+1]);
                    #pragma unroll
                    for (int j = 0; j < 4; j++) acc[mi][ni][j] = 0.f;
                }
            }
        }
    }
    __syncthreads();   // all MMA done; operand smem reusable as bbuf

    // ---- final epilogue: a = 1-z (into zbuf), b = z*tanh(h+bh) -> bbuf ----
    #pragma unroll
    for (int mi = 0; mi < 2; mi++) {
        int r0 = wm*32 + mi*16 + (lane >> 2);
        #pragma unroll
        for (int ni = 0; ni < 8; ni++) {
            int cl = wn*64 + ni*8 + (lane & 3)*2;
            #pragma unroll
            for (int hrow = 0; hrow < 2; hrow++) {
                int r = r0 + hrow*8;
                float z0 = zbuf[r*132 + cl], z1 = zbuf[r*132 + cl + 1];
                float h0 = tanhf_(acc[mi][ni][hrow*2+0] + s_bh[cl]);
                float h1 = tanhf_(acc[mi][ni][hrow*2+1] + s_bh[cl+1]);
                bbuf[r*132 + cl]     = z0*h0;
                bbuf[r*132 + cl + 1] = z1*h1;
                zbuf[r*132 + cl]     = 1.0f - z0;
                zbuf[r*132 + cl + 1] = 1.0f - z1;
            }
        }
    }
    __syncthreads();

    // ---- global a,b stores ----
    if (store_ab) {
        float* outA = dir ? g_ab2 : g_af;
        float* outB = dir ? g_bb2 : g_bf;
        #pragma unroll
        for (int i = 0; i < 16; i++) {
            int r = (tid >> 5) + i*8;
            int c4 = (tid & 31)*4;
            float4 va = *(float4*)(zbuf + r*132 + c4);
            float4 vb = *(float4*)(bbuf + r*132 + c4);
            size_t o = (size_t)(row0 + r)*256 + n0g + c4;
            *(float4*)(outA + o) = va;
            *(float4*)(outB + o) = vb;
        }
    }

    // ---- per-chunk scan composites ----
    {
        int cc = tid & 127, seg = tid >> 7;
        float pa = 1.0f, pb = 0.0f;
        if (dir == 0) {
            for (int r = seg*64; r < seg*64 + 64; r++) {
                float a = zbuf[r*132 + cc], b = bbuf[r*132 + cc];
                pb = fmaf(a, pb, b); pa *= a;
            }
        } else {
            for (int r = seg*64 + 63; r >= seg*64; r--) {
                float a = zbuf[r*132 + cc], b = bbuf[r*132 + cc];
                pb = fmaf(a, pb, b); pa *= a;
            }
        }
        s_pA[seg][cc] = pa; s_pB[seg][cc] = pb;
    }
    __syncthreads();
    if (tid < 128) {
        float A, B;
        if (dir == 0) { A = s_pA[1][tid]*s_pA[0][tid]; B = fmaf(s_pA[1][tid], s_pB[0][tid], s_pB[1][tid]); }
        else          { A = s_pA[0][tid]*s_pA[1][tid]; B = fmaf(s_pA[0][tid], s_pB[1][tid], s_pB[0][tid]); }
        size_t o = ((size_t)dir*NCH + ch)*256 + n0g + tid;
        g_cA[o] = A; g_cB[o] = B;
    }
}

// ================= scan kernels (MLP-batched) =================
__global__ __launch_bounds__(256) void scan_prefix()
{
    int dir = blockIdx.x, d = threadIdx.x;
    float cB = 0.f;
    if (dir == 0) {
        for (int c0 = 0; c0 < NCH; c0 += 8) {
            float a[8], b[8];
            #pragma unroll
            for (int i = 0; i < 8; i++) {
                a[i] = g_cA[(c0+i)*D_ + d];
                b[i] = g_cB[(c0+i)*D_ + d];
            }
            #pragma unroll
            for (int i = 0; i < 8; i++) {
                g_pref[(c0+i)*D_ + d] = cB;
                cB = fmaf(a[i], cB, b[i]);
            }
        }
    } else {
        for (int c0 = NCH - 8; c0 >= 0; c0 -= 8) {
            float a[8], b[8];
            #pragma unroll
            for (int i = 0; i < 8; i++) {
                a[i] = g_cA[(NCH + c0+i)*D_ + d];
                b[i] = g_cB[(NCH + c0+i)*D_ + d];
            }
            #pragma unroll
            for (int i = 7; i >= 0; i--) {
                g_pref[(NCH + c0+i)*D_ + d] = cB;
                cB = fmaf(a[i], cB, b[i]);
            }
        }
    }
}

__global__ __launch_bounds__(256) void scan_apply0()
{
    int d = threadIdx.x, ch = blockIdx.x;
    float h = g_pref[ch*D_ + d];
    size_t base = (size_t)ch*CHUNK*D_ + d;
    for (int j0 = 0; j0 < CHUNK; j0 += 8) {
        float a[8], b[8];
        #pragma unroll
        for (int i = 0; i < 8; i++) {
            size_t o = base + (size_t)(j0+i)*D_;
            a[i] = g_af[o]; b[i] = g_bf[o];
        }
        #pragma unroll
        for (int i = 0; i < 8; i++) {
            h = fmaf(a[i], h, b[i]);
            g_q[base + (size_t)(j0+i)*D_] = h;
        }
    }
}

__global__ __launch_bounds__(256) void scan_apply1(const float* __restrict__ story)
{
    int d = threadIdx.x, ch = blockIdx.x;
    float h = g_pref[(NCH + ch)*D_ + d];
    size_t base = ((size_t)ch*CHUNK + CHUNK-1)*D_ + d;
    for (int j0 = 0; j0 < CHUNK; j0 += 8) {
        float a[8], b[8], hf[8], x[8];
        #pragma unroll
        for (int i = 0; i < 8; i++) {
            size_t o = base - (size_t)(j0+i)*D_;
            a[i] = g_ab2[o]; b[i] = g_bb2[o];
            hf[i] = g_q[o];  x[i] = story[o];
        }
        #pragma unroll
        for (int i = 0; i < 8; i++) {
            size_t o = base - (size_t)(j0+i)*D_;
            h = fmaf(a[i], h, b[i]);
            float q = hf[i] + h;
            float u = x[i] * q;
            __nv_bfloat16 qh, ql, uh, ul;
            split2(q, qh, ql); split2(u, uh, ul);
            g_qhi[o] = qh; g_qlo[o] = ql; g_uhi[o] = uh; g_ulo[o] = ul;
        }
    }
}

__global__ __launch_bounds__(256) void scan_final(float* __restrict__ out)
{
    int d = threadIdx.x;
    float cB = 0.f;
    for (int c0 = 0; c0 < NCH; c0 += 8) {
        float a[8], b[8];
        #pragma unroll
        for (int i = 0; i < 8; i++) {
            a[i] = g_cA[(c0+i)*D_ + d];
            b[i] = g_cB[(c0+i)*D_ + d];
        }
        #pragma unroll
        for (int i = 0; i < 8; i++)
            cB = fmaf(a[i], cB, b[i]);
    }
    out[d] = cB;
}

// ================= host launcher =================
extern "C" void kernel_launch(void* const* d_in, const int* in_sizes, int n_in,
                              void* d_out, int out_size)
{
    const float* story    = (const float*)d_in[0];
    const float* question = (const float*)d_in[1];
    const float* Wz_f     = (const float*)d_in[2];
    const float* bz_f     = (const float*)d_in[3];
    const float* Wh_f     = (const float*)d_in[4];
    const float* bh_f     = (const float*)d_in[5];
    const float* Wz_b     = (const float*)d_in[6];
    const float* bz_b     = (const float*)d_in[7];
    const float* Wh_b     = (const float*)d_in[8];
    const float* bh_b     = (const float*)d_in[9];
    float* out = (float*)d_out;

    cudaFuncSetAttribute(qrn_gemm, cudaFuncAttributeMaxDynamicSharedMemorySize, SM_TOTAL);

    // weight prep: layerdir 0..4 = (f0, b0, f1, b1, f2)
    dim3 wb(32, 8), wg(8, 16, 2);
    prep_w<<<wg, wb>>>(Wz_f,            Wh_f,             0);
    prep_w<<<wg, wb>>>(Wz_b,            Wh_b,             1);
    prep_w<<<wg, wb>>>(Wz_f + 65536,    Wh_f + 131072,    2);
    prep_w<<<wg, wb>>>(Wz_b + 65536,    Wh_b + 131072,    3);
    prep_w<<<wg, wb>>>(Wz_f + 2*65536,  Wh_f + 2*131072,  4);

    prep_xu<<<T_*D_/512, 256>>>(story, question);
    qwh0<<<2, 256>>>(Wh_f, bh_f, Wh_b, bh_b, question);

    dim3 gg(2, NCH);   // (N-half, chunk)

    // ---- layer 0 ----
    qrn_gemm<<<gg, 256, SM_TOTAL>>>(0, 1, 0, 1, bz_f,        nullptr);
    qrn_gemm<<<gg, 256, SM_TOTAL>>>(1, 1, 1, 1, bz_b,        nullptr);
    scan_prefix<<<2, 256>>>();
    scan_apply0<<<NCH, 256>>>();
    scan_apply1<<<NCH, 256>>>(story);

    // ---- layer 1 ----
    qrn_gemm<<<gg, 256, SM_TOTAL>>>(2, 0, 0, 1, bz_f + 256,  bh_f + 256);
    qrn_gemm<<<gg, 256, SM_TOTAL>>>(3, 0, 1, 1, bz_b + 256,  bh_b + 256);
    scan_prefix<<<2, 256>>>();
    scan_apply0<<<NCH, 256>>>();
    scan_apply1<<<NCH, 256>>>(story);

    // ---- layer 2 (forward only; only final state needed -> composites only) ----
    qrn_gemm<<<gg, 256, SM_TOTAL>>>(4, 0, 0, 0, bz_f + 512,  bh_f + 512);
    scan_final<<<1, 256>>>(out);
}

// round 7
// speedup vs baseline: 2.9656x; 1.1762x over previous
#include <cuda_runtime.h>
#include <cuda_fp16.h>
#include <cstdint>

#define T_ 65536
#define D_ 256
#define CHUNK 128
#define NCH (T_/CHUNK)   // 512

// ================= device scratch (no allocations allowed) =================
__device__ float g_af [T_*D_];
__device__ float g_bf [T_*D_];
__device__ float g_ab2[T_*D_];
__device__ float g_bb2[T_*D_];
__device__ float g_q  [T_*D_];          // h_fwd, then q = h_fwd + h_bwd
__device__ float g_cA [2*NCH*D_];
__device__ float g_cB [2*NCH*D_];
__device__ float g_pref[2*NCH*D_];
__device__ float g_hbias[2][D_];        // layer0: bh + q0 @ Wh_bottom

__device__ __half g_xhi[T_*D_], g_xlo[T_*D_];
__device__ __half g_uhi[T_*D_], g_ulo[T_*D_];
__device__ __half g_qhi[T_*D_], g_qlo[T_*D_];
__device__ __half g_wzT[5][D_*D_];      // [layerdir][n*256+k], single fp16
__device__ __half g_whT[5][D_*2*D_];    // [layerdir][n*512+k]

// ================= helpers =================
__device__ __forceinline__ uint32_t smem_u32(const void* p) {
    uint32_t a;
    asm("{ .reg .u64 t; cvta.to.shared.u64 t, %1; cvt.u32.u64 %0, t; }" : "=r"(a) : "l"(p));
    return a;
}
__device__ __forceinline__ void ldsm_x4(uint32_t (&r)[4], uint32_t addr) {
    asm volatile("ldmatrix.sync.aligned.m8n8.x4.shared.b16 {%0,%1,%2,%3}, [%4];"
                 : "=r"(r[0]), "=r"(r[1]), "=r"(r[2]), "=r"(r[3]) : "r"(addr));
}
__device__ __forceinline__ void mma16816(float (&d)[4], const uint32_t (&a)[4], const uint32_t* b) {
    asm volatile("mma.sync.aligned.m16n8k16.row.col.f32.f16.f16.f32 "
                 "{%0,%1,%2,%3}, {%4,%5,%6,%7}, {%8,%9}, {%0,%1,%2,%3};"
                 : "+f"(d[0]), "+f"(d[1]), "+f"(d[2]), "+f"(d[3])
                 : "r"(a[0]), "r"(a[1]), "r"(a[2]), "r"(a[3]), "r"(b[0]), "r"(b[1]));
}
__device__ __forceinline__ void cpa16(uint32_t dst, const void* src) {
    asm volatile("cp.async.cg.shared.global [%0], [%1], 16;" :: "r"(dst), "l"(src));
}
#define CP_COMMIT() asm volatile("cp.async.commit_group;" ::: "memory")
#define CP_WAIT1()  asm volatile("cp.async.wait_group 1;" ::: "memory")

__device__ __forceinline__ float sigf(float v)   { return 1.0f/(1.0f+__expf(-v)); }
__device__ __forceinline__ float tanhf_(float v) { return 1.0f - 2.0f/(__expf(2.0f*v)+1.0f); }
__device__ __forceinline__ void split2h(float v, __half& h, __half& l) {
    h = __float2half_rn(v);
    l = __float2half_rn(v - __half2float(h));
}

// ================= prep kernels =================
// transpose weights to fp16: W[k][n] -> out[n][k]
__global__ void prep_w(const float* __restrict__ Wz, const float* __restrict__ Wh, int ld)
{
    int mz = blockIdx.z;                  // 0: Wz (K=256), 1: Wh (K=512)
    if (mz == 0 && blockIdx.y >= 8) return;
    const float* src = mz ? Wh : Wz;
    int Krows = mz ? 512 : 256;
    __half* dh = mz ? &g_whT[ld][0] : &g_wzT[ld][0];
    int k0 = blockIdx.y*32, n0 = blockIdx.x*32;
    int tx = threadIdx.x, ty = threadIdx.y;
    __shared__ float t[32][33];
    #pragma unroll
    for (int i = 0; i < 4; i++)
        t[ty + i*8][tx] = src[(size_t)(k0 + ty + i*8)*256 + n0 + tx];
    __syncthreads();
    #pragma unroll
    for (int i = 0; i < 4; i++)
        dh[(size_t)(n0 + ty + i*8)*Krows + k0 + tx] = __float2half_rn(t[tx][ty + i*8]);
}

// fused: x hi/lo + u0 = x*q hi/lo (single story read)
__global__ void prep_xu(const float* __restrict__ story, const float* __restrict__ q)
{
    size_t i = ((size_t)blockIdx.x*256 + threadIdx.x)*2;
    int d = (int)(i & (D_-1));
    float2 v = *(const float2*)(story + i);
    __half h0,l0,h1,l1;
    split2h(v.x,h0,l0); split2h(v.y,h1,l1);
    __half2 ph, pl; ph.x=h0; ph.y=h1; pl.x=l0; pl.y=l1;
    *(__half2*)(g_xhi+i) = ph; *(__half2*)(g_xlo+i) = pl;
    float u0 = v.x * q[d], u1 = v.y * q[d+1];
    split2h(u0,h0,l0); split2h(u1,h1,l1);
    ph.x=h0; ph.y=h1; pl.x=l0; pl.y=l1;
    *(__half2*)(g_uhi+i) = ph; *(__half2*)(g_ulo+i) = pl;
}

__global__ void qwh0(const float* __restrict__ Whf, const float* __restrict__ bhf,
                     const float* __restrict__ Whb, const float* __restrict__ bhb,
                     const float* __restrict__ q)
{
    int dir = blockIdx.x, n = threadIdx.x;
    const float* Wh = dir ? Whb : Whf;
    const float* bh = dir ? bhb : bhf;
    float acc = bh[n];
    #pragma unroll 8
    for (int k = 0; k < 256; k++)
        acc = fmaf(q[k], Wh[(size_t)(256 + k)*256 + n], acc);
    g_hbias[dir][n] = acc;
}

// ================= fused GEMM (mma.sync fp16 2-pass, cp.async pipeline) =================
// CTA: M=128 rows (one scan chunk) x N=128 channels (half). 8 warps = 4M x 2N.
// Stage (30720B): Ahi [0,10240) | Alo [10240,20480) | B [20480,30720)
// Dynamic SMEM: 3 stages (92160B), then zbuf fp32 128x132 (67584B). bbuf aliases stages.
#define STAGE_B 30720
#define NSTAGE 3
#define ZBUF_OFF (NSTAGE*STAGE_B)
#define SM_TOTAL (ZBUF_OFF + 67584)
#define TSTR 40     // smem tile row stride in halves (80 bytes)

__device__ __forceinline__ void issue_stage(int s, uint32_t sb,
    int row0, int n0g,
    const __half* wz, const __half* wh, int tid)
{
    const __half *Ah, *Al, *B; int ka, kb, Kd;
    if (s < 8)       { Ah=g_uhi; Al=g_ulo; B=wz; ka=s*32;      kb=s*32;     Kd=256; }
    else if (s < 16) { Ah=g_xhi; Al=g_xlo; B=wh; ka=(s-8)*32;  kb=(s-8)*32; Kd=512; }
    else             { Ah=g_qhi; Al=g_qlo; B=wh; ka=(s-16)*32; kb=(s-8)*32; Kd=512; }
    #pragma unroll
    for (int i = 0; i < 6; i++) {
        int v = tid + i*256;          // 0..1535
        int t = v >> 9;               // tile: 0=Ahi 1=Alo 2=B
        int c = v & 511;
        int r = c >> 2, q = c & 3;
        const __half* sp = (t==0) ? Ah : (t==1) ? Al : B;
        size_t so = (t < 2) ? ((size_t)(row0 + r)*256 + ka + q*8)
                            : ((size_t)(n0g + r)*Kd  + kb + q*8);
        uint32_t d = sb + (uint32_t)(t*10240 + r*80 + q*16);
        cpa16(d, sp + so);
    }
}

__device__ __forceinline__ void mma_step(float (&acc)[2][8][4],
    uint32_t stg, int wm, int wn, int lane)
{
    const uint32_t uA = stg, uB = stg + 20480;
    #pragma unroll
    for (int kk = 0; kk < 32; kk += 16) {
        uint32_t aH[2][4], aL[2][4], bb[8][2];
        #pragma unroll
        for (int mi = 0; mi < 2; mi++) {
            uint32_t roff = (uint32_t)(wm*32 + mi*16 + (lane & 15))*(TSTR*2)
                          + (uint32_t)(kk + ((lane >> 4) << 3))*2;
            ldsm_x4(aH[mi], uA + roff);
            ldsm_x4(aL[mi], uA + 10240 + roff);
        }
        #pragma unroll
        for (int pi = 0; pi < 4; pi++) {
            uint32_t nrow = (uint32_t)(wn*64 + pi*16 + ((lane >> 4) << 3) + (lane & 7));
            uint32_t off = nrow*(TSTR*2) + (uint32_t)(kk + (((lane >> 3) & 1) << 3))*2;
            uint32_t t[4];
            ldsm_x4(t, uB + off);
            bb[pi*2][0]=t[0]; bb[pi*2][1]=t[1]; bb[pi*2+1][0]=t[2]; bb[pi*2+1][1]=t[3];
        }
        #pragma unroll
        for (int mi = 0; mi < 2; mi++)
            #pragma unroll
            for (int ni = 0; ni < 8; ni++) {
                mma16816(acc[mi][ni], aH[mi], bb[ni]);
                mma16816(acc[mi][ni], aL[mi], bb[ni]);
            }
    }
}

__global__ __launch_bounds__(256, 1)
void qrn_gemm(int ld_f, int ld_b, int layer0, int store_ab,
              const float* __restrict__ bz_f_, const float* __restrict__ bz_b_,
              const float* __restrict__ bh_f_, const float* __restrict__ bh_b_)
{
    extern __shared__ __align__(16) char smem[];
    float* bbuf = (float*)smem;                      // aliases operand stages post-mainloop
    float* zbuf = (float*)(smem + ZBUF_OFF);
    __shared__ float s_bz[128], s_bh[128];
    __shared__ float s_pA[2][128], s_pB[2][128];

    const int tid = threadIdx.x, lane = tid & 31, warp = tid >> 5;
    const int wm = warp & 3, wn = warp >> 2;
    const int nh = blockIdx.x, ch = blockIdx.y;
    const int dir = blockIdx.z;
    const int ld = dir ? ld_b : ld_f;
    const int row0 = ch*CHUNK, n0g = nh*128;
    const uint32_t base = smem_u32(smem);

    if (tid < 128) {
        const float* bz = dir ? bz_b_ : bz_f_;
        s_bz[tid] = bz[n0g + tid];
        if (layer0) s_bh[tid] = g_hbias[dir][n0g + tid];
        else { const float* bh = dir ? bh_b_ : bh_f_; s_bh[tid] = bh[n0g + tid]; }
    }

    const __half* wz = &g_wzT[ld][0];
    const __half* wh = &g_whT[ld][0];

    const int S = layer0 ? 16 : 24;     // 8 Z-steps + 8/16 H-steps

    float acc[2][8][4];
    #pragma unroll
    for (int mi = 0; mi < 2; mi++)
        #pragma unroll
        for (int ni = 0; ni < 8; ni++)
            #pragma unroll
            for (int j = 0; j < 4; j++) acc[mi][ni][j] = 0.f;

    issue_stage(0, base + 0*STAGE_B, row0, n0g, wz, wh, tid);
    CP_COMMIT();
    issue_stage(1, base + 1*STAGE_B, row0, n0g, wz, wh, tid);
    CP_COMMIT();

    for (int s = 0; s < S; s++) {
        CP_WAIT1();
        __syncthreads();
        if (s + 2 < S)
            issue_stage(s+2, base + ((s+2) % NSTAGE)*STAGE_B, row0, n0g, wz, wh, tid);
        CP_COMMIT();

        mma_step(acc, base + (s % NSTAGE)*STAGE_B, wm, wn, lane);

        if (s == 7) {
            // z epilogue -> zbuf, reset acc for H phase
            #pragma unroll
            for (int mi = 0; mi < 2; mi++) {
                int r0 = wm*32 + mi*16 + (lane >> 2);
                #pragma unroll
                for (int ni = 0; ni < 8; ni++) {
                    int cl = wn*64 + ni*8 + (lane & 3)*2;
                    zbuf[r0*132 + cl]     = sigf(acc[mi][ni][0] + s_bz[cl]);
                    zbuf[r0*132 + cl + 1] = sigf(acc[mi][ni][1] + s_bz[cl+1]);
                    zbuf[(r0+8)*132 + cl]     = sigf(acc[mi][ni][2] + s_bz[cl]);
                    zbuf[(r0+8)*132 + cl + 1] = sigf(acc[mi][ni][3] + s_bz[cl+1]);
                    #pragma unroll
                    for (int j = 0; j < 4; j++) acc[mi][ni][j] = 0.f;
                }
            }
        }
    }
    __syncthreads();   // all MMA done; operand smem reusable as bbuf

    // ---- final epilogue: a = 1-z (into zbuf), b = z*tanh(h+bh) -> bbuf ----
    #pragma unroll
    for (int mi = 0; mi < 2; mi++) {
        int r0 = wm*32 + mi*16 + (lane >> 2);
        #pragma unroll
        for (int ni = 0; ni < 8; ni++) {
            int cl = wn*64 + ni*8 + (lane & 3)*2;
            #pragma unroll
            for (int hrow = 0; hrow < 2; hrow++) {
                int r = r0 + hrow*8;
                float z0 = zbuf[r*132 + cl], z1 = zbuf[r*132 + cl + 1];
                float h0 = tanhf_(acc[mi][ni][hrow*2+0] + s_bh[cl]);
                float h1 = tanhf_(acc[mi][ni][hrow*2+1] + s_bh[cl+1]);
                bbuf[r*132 + cl]     = z0*h0;
                bbuf[r*132 + cl + 1] = z1*h1;
                zbuf[r*132 + cl]     = 1.0f - z0;
                zbuf[r*132 + cl + 1] = 1.0f - z1;
            }
        }
    }
    __syncthreads();

    // ---- global a,b stores ----
    if (store_ab) {
        float* outA = dir ? g_ab2 : g_af;
        float* outB = dir ? g_bb2 : g_bf;
        #pragma unroll
        for (int i = 0; i < 16; i++) {
            int r = (tid >> 5) + i*8;
            int c4 = (tid & 31)*4;
            float4 va = *(float4*)(zbuf + r*132 + c4);
            float4 vb = *(float4*)(bbuf + r*132 + c4);
            size_t o = (size_t)(row0 + r)*256 + n0g + c4;
            *(float4*)(outA + o) = va;
            *(float4*)(outB + o) = vb;
        }
    }

    // ---- per-chunk scan composites ----
    {
        int cc = tid & 127, seg = tid >> 7;
        float pa = 1.0f, pb = 0.0f;
        if (dir == 0) {
            for (int r = seg*64; r < seg*64 + 64; r++) {
                float a = zbuf[r*132 + cc], b = bbuf[r*132 + cc];
                pb = fmaf(a, pb, b); pa *= a;
            }
        } else {
            for (int r = seg*64 + 63; r >= seg*64; r--) {
                float a = zbuf[r*132 + cc], b = bbuf[r*132 + cc];
                pb = fmaf(a, pb, b); pa *= a;
            }
        }
        s_pA[seg][cc] = pa; s_pB[seg][cc] = pb;
    }
    __syncthreads();
    if (tid < 128) {
        float A, B;
        if (dir == 0) { A = s_pA[1][tid]*s_pA[0][tid]; B = fmaf(s_pA[1][tid], s_pB[0][tid], s_pB[1][tid]); }
        else          { A = s_pA[0][tid]*s_pA[1][tid]; B = fmaf(s_pA[0][tid], s_pB[1][tid], s_pB[0][tid]); }
        size_t o = ((size_t)dir*NCH + ch)*256 + n0g + tid;
        g_cA[o] = A; g_cB[o] = B;
    }
}

// ================= scan kernels (MLP-batched) =================
__global__ __launch_bounds__(256) void scan_prefix()
{
    int dir = blockIdx.x, d = threadIdx.x;
    float cB = 0.f;
    if (dir == 0) {
        for (int c0 = 0; c0 < NCH; c0 += 8) {
            float a[8], b[8];
            #pragma unroll
            for (int i = 0; i < 8; i++) {
                a[i] = g_cA[(c0+i)*D_ + d];
                b[i] = g_cB[(c0+i)*D_ + d];
            }
            #pragma unroll
            for (int i = 0; i < 8; i++) {
                g_pref[(c0+i)*D_ + d] = cB;
                cB = fmaf(a[i], cB, b[i]);
            }
        }
    } else {
        for (int c0 = NCH - 8; c0 >= 0; c0 -= 8) {
            float a[8], b[8];
            #pragma unroll
            for (int i = 0; i < 8; i++) {
                a[i] = g_cA[(NCH + c0+i)*D_ + d];
                b[i] = g_cB[(NCH + c0+i)*D_ + d];
            }
            #pragma unroll
            for (int i = 7; i >= 0; i--) {
                g_pref[(NCH + c0+i)*D_ + d] = cB;
                cB = fmaf(a[i], cB, b[i]);
            }
        }
    }
}

__global__ __launch_bounds__(256) void scan_apply0()
{
    int d = threadIdx.x, ch = blockIdx.x;
    float h = g_pref[ch*D_ + d];
    size_t base = (size_t)ch*CHUNK*D_ + d;
    for (int j0 = 0; j0 < CHUNK; j0 += 8) {
        float a[8], b[8];
        #pragma unroll
        for (int i = 0; i < 8; i++) {
            size_t o = base + (size_t)(j0+i)*D_;
            a[i] = g_af[o]; b[i] = g_bf[o];
        }
        #pragma unroll
        for (int i = 0; i < 8; i++) {
            h = fmaf(a[i], h, b[i]);
            g_q[base + (size_t)(j0+i)*D_] = h;
        }
    }
}

__global__ __launch_bounds__(256) void scan_apply1(const float* __restrict__ story)
{
    int d = threadIdx.x, ch = blockIdx.x;
    float h = g_pref[(NCH + ch)*D_ + d];
    size_t base = ((size_t)ch*CHUNK + CHUNK-1)*D_ + d;
    for (int j0 = 0; j0 < CHUNK; j0 += 8) {
        float a[8], b[8], hf[8], x[8];
        #pragma unroll
        for (int i = 0; i < 8; i++) {
            size_t o = base - (size_t)(j0+i)*D_;
            a[i] = g_ab2[o]; b[i] = g_bb2[o];
            hf[i] = g_q[o];  x[i] = story[o];
        }
        #pragma unroll
        for (int i = 0; i < 8; i++) {
            size_t o = base - (size_t)(j0+i)*D_;
            h = fmaf(a[i], h, b[i]);
            float q = hf[i] + h;
            float u = x[i] * q;
            __half qh, ql, uh, ul;
            split2h(q, qh, ql); split2h(u, uh, ul);
            g_qhi[o] = qh; g_qlo[o] = ql; g_uhi[o] = uh; g_ulo[o] = ul;
        }
    }
}

__global__ __launch_bounds__(256) void scan_final(float* __restrict__ out)
{
    int d = threadIdx.x;
    float cB = 0.f;
    for (int c0 = 0; c0 < NCH; c0 += 8) {
        float a[8], b[8];
        #pragma unroll
        for (int i = 0; i < 8; i++) {
            a[i] = g_cA[(c0+i)*D_ + d];
            b[i] = g_cB[(c0+i)*D_ + d];
        }
        #pragma unroll
        for (int i = 0; i < 8; i++)
            cB = fmaf(a[i], cB, b[i]);
    }
    out[d] = cB;
}

// ================= host launcher =================
extern "C" void kernel_launch(void* const* d_in, const int* in_sizes, int n_in,
                              void* d_out, int out_size)
{
    const float* story    = (const float*)d_in[0];
    const float* question = (const float*)d_in[1];
    const float* Wz_f     = (const float*)d_in[2];
    const float* bz_f     = (const float*)d_in[3];
    const float* Wh_f     = (const float*)d_in[4];
    const float* bh_f     = (const float*)d_in[5];
    const float* Wz_b     = (const float*)d_in[6];
    const float* bz_b     = (const float*)d_in[7];
    const float* Wh_b     = (const float*)d_in[8];
    const float* bh_b     = (const float*)d_in[9];
    float* out = (float*)d_out;

    cudaFuncSetAttribute(qrn_gemm, cudaFuncAttributeMaxDynamicSharedMemorySize, SM_TOTAL);

    dim3 wb(32, 8), wg(8, 16, 2);
    // order chosen so the merged layer-0 gemm is ncu launch index 5 (-s 5 -c 1)
    prep_w<<<wg, wb>>>(Wz_f,            Wh_f,             0);   // 0
    prep_w<<<wg, wb>>>(Wz_b,            Wh_b,             1);   // 1
    prep_xu<<<T_*D_/512, 256>>>(story, question);               // 2
    qwh0<<<2, 256>>>(Wh_f, bh_f, Wh_b, bh_b, question);         // 3
    prep_w<<<wg, wb>>>(Wz_f + 65536,    Wh_f + 131072,    2);   // 4

    dim3 gg2(2, NCH, 2);   // (N-half, chunk, dir)
    dim3 gg1(2, NCH, 1);

    // ---- layer 0 (fwd+bwd merged) ----                        // 5 <- ncu capture
    qrn_gemm<<<gg2, 256, SM_TOTAL>>>(0, 1, 1, 1, bz_f, bz_b, nullptr, nullptr);
    prep_w<<<wg, wb>>>(Wz_b + 65536,    Wh_b + 131072,    3);   // 6
    prep_w<<<wg, wb>>>(Wz_f + 2*65536,  Wh_f + 2*131072,  4);   // 7
    scan_prefix<<<2, 256>>>();
    scan_apply0<<<NCH, 256>>>();
    scan_apply1<<<NCH, 256>>>(story);

    // ---- layer 1 ----
    qrn_gemm<<<gg2, 256, SM_TOTAL>>>(2, 3, 0, 1, bz_f + 256, bz_b + 256, bh_f + 256, bh_b + 256);
    scan_prefix<<<2, 256>>>();
    scan_apply0<<<NCH, 256>>>();
    scan_apply1<<<NCH, 256>>>(story);

    // ---- layer 2 (forward only; composites only) ----
    qrn_gemm<<<gg1, 256, SM_TOTAL>>>(4, 4, 0, 0, bz_f + 512, bz_b + 512, bh_f + 512, bh_b + 512);
    scan_final<<<1, 256>>>(out);
}